// round 16
// baseline (speedup 1.0000x reference)
#include <cuda_runtime.h>
#include <cuda_bf16.h>
#include <math.h>
#include <stdint.h>

#define LL 2
#define NN1 8
#define NN2 8
#define PP 1024
#define DD 768
#define PH 32
#define PW 32
#define IMG 512

// Blocked-swizzled bf16 storage: per matrix (1024x768): 8 rowblocks x 12
// kblocks of contiguous 16KB tiles; tile interior = 128 rows x 8 chunks of
// 16B with chunk' = chunk ^ (row & 7). Matrix stride = 96 tiles = 1.5 MB.
#define TILE_B 16384
#define MAT_B (96 * TILE_B)   // 1572864 bytes

__device__ __nv_bfloat16 g_fa[LL * NN1 * PP * DD];  // blocked-swizzled
__device__ __nv_bfloat16 g_fb[LL * NN2 * PP * DD];  // blocked-swizzled
__device__ float g_md2[2 * LL * NN1 * NN2 * PP];    // per-column-half row max
__device__ float g_spbar[NN1 * PP];

// ---------------------------------------------------------------------------
// Kernel 1: L2-normalize rows of [rows, 768] -> bf16 in blocked-swizzled
// layout. One warp per row; lane handles chunks c = lane, lane+32, lane+64.
// ---------------------------------------------------------------------------
__global__ __launch_bounds__(256) void normalize_kernel(const float* __restrict__ inA,
                                                        const float* __restrict__ inB,
                                                        int nrows) {
    int row  = blockIdx.x * 8 + (threadIdx.x >> 5);
    int lane = threadIdx.x & 31;
    if (row >= nrows) return;
    const float* in = blockIdx.y ? inB : inA;
    char* outb = (char*)(blockIdx.y ? g_fb : g_fa);
    const float4* src = (const float4*)(in + (size_t)row * DD);

    float4 v[6];
    float ss = 0.f;
#pragma unroll
    for (int i = 0; i < 3; i++) {
        v[2 * i + 0] = src[2 * lane + 64 * i];
        v[2 * i + 1] = src[2 * lane + 64 * i + 1];
        ss += v[2*i].x * v[2*i].x + v[2*i].y * v[2*i].y
            + v[2*i].z * v[2*i].z + v[2*i].w * v[2*i].w;
        ss += v[2*i+1].x * v[2*i+1].x + v[2*i+1].y * v[2*i+1].y
            + v[2*i+1].z * v[2*i+1].z + v[2*i+1].w * v[2*i+1].w;
    }
#pragma unroll
    for (int o = 16; o > 0; o >>= 1) ss += __shfl_xor_sync(0xffffffffu, ss, o);
    float inv = 1.0f / sqrtf(ss);

    const int rm = row & (PP - 1);       // row within matrix
    const size_t matoff = (size_t)(row >> 10) * MAT_B;
    const int r7 = rm & 127;
    const uint32_t inner = (uint32_t)(r7 * 128);

#pragma unroll
    for (int i = 0; i < 3; i++) {
        int c = lane + 32 * i;
        __nv_bfloat162 h0 = __floats2bfloat162_rn(v[2*i].x * inv,   v[2*i].y * inv);
        __nv_bfloat162 h1 = __floats2bfloat162_rn(v[2*i].z * inv,   v[2*i].w * inv);
        __nv_bfloat162 h2 = __floats2bfloat162_rn(v[2*i+1].x * inv, v[2*i+1].y * inv);
        __nv_bfloat162 h3 = __floats2bfloat162_rn(v[2*i+1].z * inv, v[2*i+1].w * inv);
        uint4 u;
        u.x = *(uint32_t*)&h0; u.y = *(uint32_t*)&h1;
        u.z = *(uint32_t*)&h2; u.w = *(uint32_t*)&h3;
        size_t addr = matoff
                    + ((size_t)((rm >> 7) * 12 + (c >> 3)) << 14)
                    + inner
                    + (uint32_t)((((c & 7) ^ (r7 & 7)) & 7) << 4);
        *(uint4*)(outb + addr) = u;
    }
}

// ---------------------------------------------------------------------------
// Kernel 2: fused bf16 mma.sync GEMM + row-max (v11 = v10 persistent).
// Grid: 296 CTAs (2/SM); each loops tiles t = blockIdx.x + k*gridDim.x over
// 2048 tiles (pair(128) x rowblk(8) x colhalf(2)). The mbarrier pipeline and
// global stage counters run continuously across tiles: one prime per CTA.
// Per tile: 48 stages (4 col tiles x 12 K-steps of 64). 256 thr = 8 warps
// (2m x 4n), warp tile 64x32, mma.m16n8k16.bf16, bulk-copy TMA into 3-slot
// ring; full[j] expect_tx / empty[j] 8 warp-arrives.
// ---------------------------------------------------------------------------
#define BM 128
#define BN 128
#define ABUF 16384            // A tile in slot
#define SLOT (2 * ABUF)       // A+B per ring slot = 32768 B
#define OFF_PART (3 * SLOT)   // 98304
#define SMEM_BYTES (OFF_PART + 4 * 128 * 4)  // 100352
#define NTILE 2048
#define NCTA 296

__device__ __forceinline__ void ldsm4(uint32_t* r, uint32_t addr) {
    asm volatile("ldmatrix.sync.aligned.m8n8.x4.shared.b16 {%0,%1,%2,%3}, [%4];"
                 : "=r"(r[0]), "=r"(r[1]), "=r"(r[2]), "=r"(r[3]) : "r"(addr));
}

__device__ __forceinline__ void mbar_wait(uint32_t addr, int parity) {
    asm volatile(
        "{\n\t"
        ".reg .pred P1;\n\t"
        "WL_%=:\n\t"
        "mbarrier.try_wait.parity.acquire.cta.shared::cta.b64 P1, [%0], %1, 0x989680;\n\t"
        "@P1 bra.uni WD_%=;\n\t"
        "bra.uni WL_%=;\n\t"
        "WD_%=:\n\t"
        "}"
        :: "r"(addr), "r"(parity) : "memory");
}

__global__ __launch_bounds__(256, 2) void distmax_bf16_v11() {
    extern __shared__ char dsm[];
    __shared__ __align__(8) uint64_t full_s[3];
    __shared__ __align__(8) uint64_t empty_s[3];
    uint32_t sm = (uint32_t)__cvta_generic_to_shared(dsm);
    uint32_t fb = (uint32_t)__cvta_generic_to_shared(full_s);
    uint32_t eb = (uint32_t)__cvta_generic_to_shared(empty_s);
    float* part = (float*)(dsm + OFF_PART);

    const int tid  = threadIdx.x;
    const int lane = tid & 31;
    const int warp = tid >> 5;
    const int wm = warp >> 2;        // 0..1
    const int wn = warp & 3;         // 0..3
    const int g  = lane >> 2;        // 0..7
    const int t4 = lane & 3;         // 0..3
    const int sub = lane >> 3;       // 0..3 (ldmatrix sub-matrix)
    const int lr8 = lane & 7;

    if (tid == 0) {
#pragma unroll
        for (int j = 0; j < 3; j++) {
            asm volatile("mbarrier.init.shared.b64 [%0], %1;"
                         :: "r"(fb + 8 * j), "r"(1) : "memory");
            asm volatile("mbarrier.init.shared.b64 [%0], %1;"
                         :: "r"(eb + 8 * j), "r"(8) : "memory");
        }
    }
    __syncthreads();

    // ldmatrix addressing (proven fragment map + swizzle):
    const uint32_t aRow = (uint32_t)((wm * 64 + (sub & 1) * 8 + lr8) * 128);
    const uint32_t bRow = (uint32_t)((wn * 32 + (sub >> 1) * 8 + lr8) * 128);
    uint32_t aCk[4], bCk[4];
#pragma unroll
    for (int k16 = 0; k16 < 4; k16++) {
        aCk[k16] = (uint32_t)(((((sub >> 1) + 2 * k16) ^ lr8) & 7) * 16);
        bCk[k16] = (uint32_t)(((((sub & 1) + 2 * k16) ^ lr8) & 7) * 16);
    }

    // ---- issue-side iterator (global stage t; tile it_tile, stage it_s) ----
    int it_tile = blockIdx.x;
    int it_s = 0;
    int t_is = 0;
    auto issue = [&]() {
        if (it_tile < NTILE) {
            if (tid == 0) {
                int j = t_is % 3;
                int k = t_is / 3;
                if (k >= 1) mbar_wait(eb + (uint32_t)(j * 8), (k - 1) & 1);
                int pair = it_tile >> 4;
                int subt = it_tile & 15;
                int rowblk = subt & 7;
                int half = subt >> 3;
                int l = pair >> 6, n1 = (pair >> 3) & 7, n2 = pair & 7;
                int kk = it_s % 12;
                int ct = half * 4 + it_s / 12;
                const char* asrc = (const char*)g_fa + (size_t)(l * NN1 + n1) * MAT_B
                                 + ((size_t)(rowblk * 12 + kk) << 14);
                const char* bsrc = (const char*)g_fb + (size_t)(l * NN2 + n2) * MAT_B
                                 + ((size_t)(ct * 12 + kk) << 14);
                uint32_t bar = fb + (uint32_t)(j * 8);
                uint32_t dst = sm + (uint32_t)(j * SLOT);
                asm volatile("fence.proxy.async.shared::cta;" ::: "memory");
                asm volatile("mbarrier.arrive.expect_tx.shared.b64 _, [%0], %1;"
                             :: "r"(bar), "r"(2 * ABUF) : "memory");
                asm volatile(
                    "cp.async.bulk.shared::cluster.global.mbarrier::complete_tx::bytes "
                    "[%0], [%1], %2, [%3];"
                    :: "r"(dst), "l"(asrc), "r"(ABUF), "r"(bar) : "memory");
                asm volatile(
                    "cp.async.bulk.shared::cluster.global.mbarrier::complete_tx::bytes "
                    "[%0], [%1], %2, [%3];"
                    :: "r"(dst + ABUF), "l"(bsrc), "r"(ABUF), "r"(bar) : "memory");
            }
            t_is++;
            if (++it_s == 48) { it_s = 0; it_tile += gridDim.x; }
        }
    };

    issue();   // global stage 0
    issue();   // global stage 1

    float acc[4][4][4];
    int cs = 0;   // global compute stage counter

    for (int tile = blockIdx.x; tile < NTILE; tile += gridDim.x) {
        const int pair = tile >> 4;
        const int subt = tile & 15;
        const int rowblk = subt & 7;
        const int half = subt >> 3;

        float rmax[4][2];
#pragma unroll
        for (int i = 0; i < 4; i++) { rmax[i][0] = -2.f; rmax[i][1] = -2.f; }

        for (int si = 0; si < 48; si++) {
            issue();                                   // global stage cs+2
            const int cb = cs % 3;
            mbar_wait(fb + (uint32_t)(cb * 8), (cs / 3) & 1);

            const int kc = si % 12;
            if (kc == 0) {
#pragma unroll
                for (int mi = 0; mi < 4; mi++)
#pragma unroll
                    for (int ni = 0; ni < 4; ni++)
#pragma unroll
                        for (int r = 0; r < 4; r++) acc[mi][ni][r] = 0.f;
            }

            const uint32_t aBuf = sm + (uint32_t)(cb * SLOT);
            const uint32_t bBuf = aBuf + ABUF;

#pragma unroll
            for (int k16 = 0; k16 < 4; k16++) {
                uint32_t a[4][4], b[2][4];
#pragma unroll
                for (int mi = 0; mi < 4; mi++)
                    ldsm4(a[mi], aBuf + aRow + (uint32_t)(mi * 2048) + aCk[k16]);
#pragma unroll
                for (int np = 0; np < 2; np++)
                    ldsm4(b[np], bBuf + bRow + (uint32_t)(np * 2048) + bCk[k16]);
#pragma unroll
                for (int mi = 0; mi < 4; mi++)
#pragma unroll
                    for (int ni = 0; ni < 4; ni++) {
                        asm volatile(
                            "mma.sync.aligned.m16n8k16.row.col.f32.bf16.bf16.f32 "
                            "{%0,%1,%2,%3},{%4,%5,%6,%7},{%8,%9},{%0,%1,%2,%3};\n"
                            : "+f"(acc[mi][ni][0]), "+f"(acc[mi][ni][1]),
                              "+f"(acc[mi][ni][2]), "+f"(acc[mi][ni][3])
                            : "r"(a[mi][0]), "r"(a[mi][1]), "r"(a[mi][2]), "r"(a[mi][3]),
                              "r"(b[ni >> 1][(ni & 1) * 2]), "r"(b[ni >> 1][(ni & 1) * 2 + 1]));
                    }
            }

            // warp done reading slot cb (ldmatrix warp-synchronous): release.
            if (lane == 0)
                asm volatile("mbarrier.arrive.shared.b64 _, [%0];"
                             :: "r"(eb + (uint32_t)(cb * 8)) : "memory");

            if (kc == 11) {
#pragma unroll
                for (int mi = 0; mi < 4; mi++) {
                    float m0 = -2.f, m1 = -2.f;
#pragma unroll
                    for (int ni = 0; ni < 4; ni++) {
                        m0 = fmaxf(m0, fmaxf(acc[mi][ni][0], acc[mi][ni][1]));
                        m1 = fmaxf(m1, fmaxf(acc[mi][ni][2], acc[mi][ni][3]));
                    }
                    rmax[mi][0] = fmaxf(rmax[mi][0], m0);
                    rmax[mi][1] = fmaxf(rmax[mi][1], m1);
                }
            }
            cs++;
        }

        // ---- per-tile epilogue ----
#pragma unroll
        for (int o = 1; o <= 2; o <<= 1) {
#pragma unroll
            for (int mi = 0; mi < 4; mi++) {
                rmax[mi][0] = fmaxf(rmax[mi][0], __shfl_xor_sync(0xffffffffu, rmax[mi][0], o));
                rmax[mi][1] = fmaxf(rmax[mi][1], __shfl_xor_sync(0xffffffffu, rmax[mi][1], o));
            }
        }
        if (t4 == 0) {
#pragma unroll
            for (int mi = 0; mi < 4; mi++) {
                int r = wm * 64 + mi * 16 + g;
                part[wn * 128 + r] = rmax[mi][0];
                part[wn * 128 + r + 8] = rmax[mi][1];
            }
        }
        __syncthreads();
        if (tid < 128) {
            float v = fmaxf(fmaxf(part[tid], part[128 + tid]),
                            fmaxf(part[256 + tid], part[384 + tid]));
            g_md2[(size_t)half * (128 * PP) + (size_t)pair * PP + rowblk * BM + tid] = v;
        }
        __syncthreads();   // part[] reuse guard for next tile
    }
}

// ---------------------------------------------------------------------------
// Kernel 3 (fused): per n1: combine halves, sp, spbar, per-pair max over p,
// scores -> out[0..7]. One block per n1, 1024 threads (one per p).
// ---------------------------------------------------------------------------
__global__ __launch_bounds__(1024) void spfused_kernel(const float* __restrict__ mask,
                                                       float* __restrict__ out) {
    const int n1 = blockIdx.x;
    const int p  = threadIdx.x;
    const int lane = p & 31;
    const int warp = p >> 5;
    __shared__ float wmax[32][16];
    __shared__ float score[16];

    float mk = mask[n1 * PP + p];
    float sum = 0.f;
    float sps[16];
#pragma unroll
    for (int l = 0; l < LL; l++)
#pragma unroll
        for (int n2 = 0; n2 < NN2; n2++) {
            int w = l * NN2 + n2;
            int pr = (l * NN1 + n1) * NN2 + n2;
            float s = fmaxf(g_md2[pr * PP + p], g_md2[128 * PP + pr * PP + p]);
            float d2 = fmaxf(2.0f - 2.0f * s, 1e-12f);
            float sp = sqrtf(d2) * 0.5f * mk;
            sum += sp;
            sps[w] = sp;
        }
    g_spbar[n1 * PP + p] = sum * (1.0f / 16.0f);

#pragma unroll
    for (int o = 16; o > 0; o >>= 1)
#pragma unroll
        for (int w = 0; w < 16; w++)
            sps[w] = fmaxf(sps[w], __shfl_xor_sync(0xffffffffu, sps[w], o));
    if (lane == 0)
#pragma unroll
        for (int w = 0; w < 16; w++) wmax[warp][w] = sps[w];
    __syncthreads();

    if (warp < 16) {
        float m = wmax[lane][warp];
#pragma unroll
        for (int o = 16; o > 0; o >>= 1)
            m = fmaxf(m, __shfl_xor_sync(0xffffffffu, m, o));
        if (lane == 0) score[warp] = m;
    }
    __syncthreads();
    if (p == 0) {
        float s = 0.f;
#pragma unroll
        for (int w = 0; w < 16; w++) s += score[w];
        out[n1] = s * (1.0f / 16.0f);
    }
}

// ---------------------------------------------------------------------------
// Kernel 4: bilinear resize 32x32 -> 512x512, 4 px per thread (float4 store).
// ---------------------------------------------------------------------------
__global__ __launch_bounds__(256) void resize_kernel(float* __restrict__ out) {
    int idx = blockIdx.x * 256 + threadIdx.x;          // NN1*512*128 threads
    if (idx >= NN1 * IMG * (IMG / 4)) return;
    int n1  = idx >> 16;                // 512*128 per n1
    int rem = idx & 65535;
    int y  = rem >> 7;
    int xq = rem & 127;

    float sy = (y + 0.5f) * (1.0f / 16.0f) - 0.5f;
    int y0 = (int)floorf(sy);
    float wy = sy - (float)y0;
    int y0c = min(max(y0, 0), PH - 1);
    int y1c = min(max(y0 + 1, 0), PH - 1);

    const float* r0 = g_spbar + n1 * PP + y0c * PW;
    const float* r1 = g_spbar + n1 * PP + y1c * PW;

    float res[4];
#pragma unroll
    for (int j = 0; j < 4; j++) {
        int x = xq * 4 + j;
        float sx = (x + 0.5f) * (1.0f / 16.0f) - 0.5f;
        int x0 = (int)floorf(sx);
        float wx = sx - (float)x0;
        int x0c = min(max(x0, 0), PW - 1);
        int x1c = min(max(x0 + 1, 0), PW - 1);
        float top = (1.f - wx) * r0[x0c] + wx * r0[x1c];
        float bot = (1.f - wx) * r1[x0c] + wx * r1[x1c];
        res[j] = (1.f - wy) * top + wy * bot;
    }
    float4 v4 = make_float4(res[0], res[1], res[2], res[3]);
    *(float4*)(out + 8 + (size_t)n1 * IMG * IMG + y * IMG + xq * 4) = v4;
}

// ---------------------------------------------------------------------------
extern "C" void kernel_launch(void* const* d_in, const int* in_sizes, int n_in,
                              void* d_out, int out_size) {
    const float* feats  = (const float*)d_in[0];
    const float* nfeats = (const float*)d_in[1];
    const float* mask   = (const float*)d_in[2];
    float* out = (float*)d_out;

    const int rows = LL * NN1 * PP;  // 16384 rows per tensor

    dim3 ngrid(rows / 8, 2);
    normalize_kernel<<<ngrid, 256>>>(feats, nfeats, rows);

    cudaFuncSetAttribute(distmax_bf16_v11,
                         cudaFuncAttributeMaxDynamicSharedMemorySize, SMEM_BYTES);
    distmax_bf16_v11<<<NCTA, 256, SMEM_BYTES>>>();

    spfused_kernel<<<NN1, 1024>>>(mask, out);
    resize_kernel<<<(NN1 * IMG * (IMG / 4) + 255) / 256, 256>>>(out);
}

// round 17
// speedup vs baseline: 1.0985x; 1.0985x over previous
#include <cuda_runtime.h>
#include <cuda_bf16.h>
#include <math.h>
#include <stdint.h>

#define LL 2
#define NN1 8
#define NN2 8
#define PP 1024
#define DD 768
#define PH 32
#define PW 32
#define IMG 512

// Blocked-swizzled bf16 storage: per matrix (1024x768): 8 rowblocks x 12
// kblocks of contiguous 16KB tiles; tile interior = 128 rows x 8 chunks of
// 16B with chunk' = chunk ^ (row & 7). Matrix stride = 96 tiles = 1.5 MB.
#define TILE_B 16384
#define MAT_B (96 * TILE_B)   // 1572864 bytes

__device__ __nv_bfloat16 g_fa[LL * NN1 * PP * DD];  // blocked-swizzled
__device__ __nv_bfloat16 g_fb[LL * NN2 * PP * DD];  // blocked-swizzled
__device__ float g_md2[2 * LL * NN1 * NN2 * PP];    // per-column-half row max
__device__ float g_spbar[NN1 * PP];

// ---------------------------------------------------------------------------
// Kernel 1: L2-normalize rows of [rows, 768] -> bf16 in blocked-swizzled
// layout. One warp per row; lane handles chunks c = lane, lane+32, lane+64.
// ---------------------------------------------------------------------------
__global__ __launch_bounds__(256) void normalize_kernel(const float* __restrict__ inA,
                                                        const float* __restrict__ inB,
                                                        int nrows) {
    int row  = blockIdx.x * 8 + (threadIdx.x >> 5);
    int lane = threadIdx.x & 31;
    if (row >= nrows) return;
    const float* in = blockIdx.y ? inB : inA;
    char* outb = (char*)(blockIdx.y ? g_fb : g_fa);
    const float4* src = (const float4*)(in + (size_t)row * DD);

    float4 v[6];
    float ss = 0.f;
#pragma unroll
    for (int i = 0; i < 3; i++) {
        v[2 * i + 0] = src[2 * lane + 64 * i];
        v[2 * i + 1] = src[2 * lane + 64 * i + 1];
        ss += v[2*i].x * v[2*i].x + v[2*i].y * v[2*i].y
            + v[2*i].z * v[2*i].z + v[2*i].w * v[2*i].w;
        ss += v[2*i+1].x * v[2*i+1].x + v[2*i+1].y * v[2*i+1].y
            + v[2*i+1].z * v[2*i+1].z + v[2*i+1].w * v[2*i+1].w;
    }
#pragma unroll
    for (int o = 16; o > 0; o >>= 1) ss += __shfl_xor_sync(0xffffffffu, ss, o);
    float inv = 1.0f / sqrtf(ss);

    const int rm = row & (PP - 1);       // row within matrix
    const size_t matoff = (size_t)(row >> 10) * MAT_B;
    const int r7 = rm & 127;
    const uint32_t inner = (uint32_t)(r7 * 128);

#pragma unroll
    for (int i = 0; i < 3; i++) {
        int c = lane + 32 * i;
        __nv_bfloat162 h0 = __floats2bfloat162_rn(v[2*i].x * inv,   v[2*i].y * inv);
        __nv_bfloat162 h1 = __floats2bfloat162_rn(v[2*i].z * inv,   v[2*i].w * inv);
        __nv_bfloat162 h2 = __floats2bfloat162_rn(v[2*i+1].x * inv, v[2*i+1].y * inv);
        __nv_bfloat162 h3 = __floats2bfloat162_rn(v[2*i+1].z * inv, v[2*i+1].w * inv);
        uint4 u;
        u.x = *(uint32_t*)&h0; u.y = *(uint32_t*)&h1;
        u.z = *(uint32_t*)&h2; u.w = *(uint32_t*)&h3;
        size_t addr = matoff
                    + ((size_t)((rm >> 7) * 12 + (c >> 3)) << 14)
                    + inner
                    + (uint32_t)((((c & 7) ^ (r7 & 7)) & 7) << 4);
        *(uint4*)(outb + addr) = u;
    }
}

// ---------------------------------------------------------------------------
// Kernel 2: fused bf16 mma.sync GEMM + row-max (v10 — PROVEN 436us config).
// Grid (16,128): blockIdx.x = rowblock(8) x colhalf(2). Each CTA: 128-row
// strip of A x 4 column tiles of 128 = flat 48-stage pipeline. Per stage:
// thread 0 issues 2 x 16KB cp.async.bulk into a 3-slot ring; full[j]
// (expect_tx) signals data, empty[j] (8 warp-arrives) signals consumption.
// 256 thr = 8 warps (2m x 4n), warp tile 64x32, mma.m16n8k16.bf16, 2 CTAs/SM.
// ---------------------------------------------------------------------------
#define BM 128
#define BN 128
#define ABUF 16384            // A tile in slot
#define SLOT (2 * ABUF)       // A+B per ring slot = 32768 B
#define OFF_PART (3 * SLOT)   // 98304
#define SMEM_BYTES (OFF_PART + 4 * 128 * 4)  // 100352
#define NSTG 48               // 4 column tiles x 12 K-stages

__device__ __forceinline__ void ldsm4(uint32_t* r, uint32_t addr) {
    asm volatile("ldmatrix.sync.aligned.m8n8.x4.shared.b16 {%0,%1,%2,%3}, [%4];"
                 : "=r"(r[0]), "=r"(r[1]), "=r"(r[2]), "=r"(r[3]) : "r"(addr));
}

__device__ __forceinline__ void mbar_wait(uint32_t addr, int parity) {
    asm volatile(
        "{\n\t"
        ".reg .pred P1;\n\t"
        "WL_%=:\n\t"
        "mbarrier.try_wait.parity.acquire.cta.shared::cta.b64 P1, [%0], %1, 0x989680;\n\t"
        "@P1 bra.uni WD_%=;\n\t"
        "bra.uni WL_%=;\n\t"
        "WD_%=:\n\t"
        "}"
        :: "r"(addr), "r"(parity) : "memory");
}

__global__ __launch_bounds__(256, 2) void distmax_bf16_v10() {
    extern __shared__ char dsm[];
    __shared__ __align__(8) uint64_t full_s[3];
    __shared__ __align__(8) uint64_t empty_s[3];
    uint32_t sm = (uint32_t)__cvta_generic_to_shared(dsm);
    uint32_t fb = (uint32_t)__cvta_generic_to_shared(full_s);
    uint32_t eb = (uint32_t)__cvta_generic_to_shared(empty_s);
    float* part = (float*)(dsm + OFF_PART);

    const int pair = blockIdx.y;          // ((l*8 + n1)*8 + n2)
    const int l  = pair >> 6;
    const int n1 = (pair >> 3) & 7;
    const int n2 = pair & 7;
    const int rowblk = blockIdx.x & 7;
    const int half   = blockIdx.x >> 3;   // column tiles [half*4, half*4+4)
    const char* Abase = (const char*)g_fa + (size_t)(l * NN1 + n1) * MAT_B;
    const char* Bbase = (const char*)g_fb + (size_t)(l * NN2 + n2) * MAT_B;

    const int tid  = threadIdx.x;
    const int lane = tid & 31;
    const int warp = tid >> 5;
    const int wm = warp >> 2;        // 0..1
    const int wn = warp & 3;         // 0..3
    const int g  = lane >> 2;        // 0..7
    const int t4 = lane & 3;         // 0..3
    const int sub = lane >> 3;       // 0..3 (ldmatrix sub-matrix)
    const int lr8 = lane & 7;

    if (tid == 0) {
#pragma unroll
        for (int j = 0; j < 3; j++) {
            asm volatile("mbarrier.init.shared.b64 [%0], %1;"
                         :: "r"(fb + 8 * j), "r"(1) : "memory");
            asm volatile("mbarrier.init.shared.b64 [%0], %1;"
                         :: "r"(eb + 8 * j), "r"(8) : "memory");
        }
    }
    __syncthreads();

    // ldmatrix addressing (proven fragment map + swizzle):
    const uint32_t aRow = (uint32_t)((wm * 64 + (sub & 1) * 8 + lr8) * 128);
    const uint32_t bRow = (uint32_t)((wn * 32 + (sub >> 1) * 8 + lr8) * 128);
    uint32_t aCk[4], bCk[4];
#pragma unroll
    for (int k16 = 0; k16 < 4; k16++) {
        aCk[k16] = (uint32_t)(((((sub >> 1) + 2 * k16) ^ lr8) & 7) * 16);
        bCk[k16] = (uint32_t)(((((sub & 1) + 2 * k16) ^ lr8) & 7) * 16);
    }

    float rmax[4][2];
#pragma unroll
    for (int i = 0; i < 4; i++) { rmax[i][0] = -2.f; rmax[i][1] = -2.f; }

    // issue(t): thread0 bulk-copies stage t's A+B tiles into slot t%3.
    // For t>=3, first wait consumption #(t/3 - 1) of that slot.
    int ct_n = half * 4, k_n = 0;   // (ct,k) of next stage to issue
    auto issue = [&](int t) {
        if (tid == 0) {
            int j = t % 3;
            int k = t / 3;
            if (k >= 1) mbar_wait(eb + (uint32_t)(j * 8), (k - 1) & 1);
            uint32_t bar = fb + (uint32_t)(j * 8);
            uint32_t dst = sm + (uint32_t)(j * SLOT);
            const char* asrc = Abase + ((size_t)(rowblk * 12 + k_n) << 14);
            const char* bsrc = Bbase + ((size_t)(ct_n * 12 + k_n) << 14);
            asm volatile("fence.proxy.async.shared::cta;" ::: "memory");
            asm volatile("mbarrier.arrive.expect_tx.shared.b64 _, [%0], %1;"
                         :: "r"(bar), "r"(2 * ABUF) : "memory");
            asm volatile(
                "cp.async.bulk.shared::cluster.global.mbarrier::complete_tx::bytes "
                "[%0], [%1], %2, [%3];"
                :: "r"(dst), "l"(asrc), "r"(ABUF), "r"(bar) : "memory");
            asm volatile(
                "cp.async.bulk.shared::cluster.global.mbarrier::complete_tx::bytes "
                "[%0], [%1], %2, [%3];"
                :: "r"(dst + ABUF), "l"(bsrc), "r"(ABUF), "r"(bar) : "memory");
        }
        if (++k_n == 12) { k_n = 0; ct_n++; }
    };

    issue(0);
    issue(1);

    float acc[4][4][4];
    int kc = 0;   // kstep within current column tile
    int cb = 0;   // ring slot of current compute stage

    for (int s = 0; s < NSTG; s++) {
        if (s + 2 < NSTG) issue(s + 2);
        // Acquire-wait: stage-s data visible to this thread.
        mbar_wait(fb + (uint32_t)(cb * 8), (s / 3) & 1);

        if (kc == 0) {
#pragma unroll
            for (int mi = 0; mi < 4; mi++)
#pragma unroll
                for (int ni = 0; ni < 4; ni++)
#pragma unroll
                    for (int r = 0; r < 4; r++) acc[mi][ni][r] = 0.f;
        }

        const uint32_t aBuf = sm + (uint32_t)(cb * SLOT);
        const uint32_t bBuf = aBuf + ABUF;

#pragma unroll
        for (int k16 = 0; k16 < 4; k16++) {
            uint32_t a[4][4], b[2][4];
#pragma unroll
            for (int mi = 0; mi < 4; mi++)
                ldsm4(a[mi], aBuf + aRow + (uint32_t)(mi * 2048) + aCk[k16]);
#pragma unroll
            for (int np = 0; np < 2; np++)
                ldsm4(b[np], bBuf + bRow + (uint32_t)(np * 2048) + bCk[k16]);
#pragma unroll
            for (int mi = 0; mi < 4; mi++)
#pragma unroll
                for (int ni = 0; ni < 4; ni++) {
                    asm volatile(
                        "mma.sync.aligned.m16n8k16.row.col.f32.bf16.bf16.f32 "
                        "{%0,%1,%2,%3},{%4,%5,%6,%7},{%8,%9},{%0,%1,%2,%3};\n"
                        : "+f"(acc[mi][ni][0]), "+f"(acc[mi][ni][1]),
                          "+f"(acc[mi][ni][2]), "+f"(acc[mi][ni][3])
                        : "r"(a[mi][0]), "r"(a[mi][1]), "r"(a[mi][2]), "r"(a[mi][3]),
                          "r"(b[ni >> 1][(ni & 1) * 2]), "r"(b[ni >> 1][(ni & 1) * 2 + 1]));
                }
        }

        // This warp is done reading slot cb for stage s (ldmatrix is
        // warp-synchronous, so all lanes' reads retired). Release-arrive.
        if (lane == 0)
            asm volatile("mbarrier.arrive.shared.b64 _, [%0];"
                         :: "r"(eb + (uint32_t)(cb * 8)) : "memory");

        if (kc == 11) {
            // column tile finished: fold into running row max
#pragma unroll
            for (int mi = 0; mi < 4; mi++) {
                float m0 = -2.f, m1 = -2.f;
#pragma unroll
                for (int ni = 0; ni < 4; ni++) {
                    m0 = fmaxf(m0, fmaxf(acc[mi][ni][0], acc[mi][ni][1]));
                    m1 = fmaxf(m1, fmaxf(acc[mi][ni][2], acc[mi][ni][3]));
                }
                rmax[mi][0] = fmaxf(rmax[mi][0], m0);
                rmax[mi][1] = fmaxf(rmax[mi][1], m1);
            }
            kc = 0;
        } else {
            kc++;
        }
        if (++cb == 3) cb = 0;
    }

    // reduce across the 4 lanes sharing g (t4 = lane&3)
#pragma unroll
    for (int o = 1; o <= 2; o <<= 1) {
#pragma unroll
        for (int mi = 0; mi < 4; mi++) {
            rmax[mi][0] = fmaxf(rmax[mi][0], __shfl_xor_sync(0xffffffffu, rmax[mi][0], o));
            rmax[mi][1] = fmaxf(rmax[mi][1], __shfl_xor_sync(0xffffffffu, rmax[mi][1], o));
        }
    }
    if (t4 == 0) {
#pragma unroll
        for (int mi = 0; mi < 4; mi++) {
            int r = wm * 64 + mi * 16 + g;
            part[wn * 128 + r] = rmax[mi][0];
            part[wn * 128 + r + 8] = rmax[mi][1];
        }
    }
    __syncthreads();
    if (tid < 128) {
        float v = fmaxf(fmaxf(part[tid], part[128 + tid]),
                        fmaxf(part[256 + tid], part[384 + tid]));
        g_md2[(size_t)half * (128 * PP) + (size_t)pair * PP + rowblk * BM + tid] = v;
    }
}

// ---------------------------------------------------------------------------
// Kernel 3 (fused): per n1: combine halves, sp, spbar, per-pair max over p,
// scores -> out[0..7]. One block per n1, 1024 threads (one per p).
// ---------------------------------------------------------------------------
__global__ __launch_bounds__(1024) void spfused_kernel(const float* __restrict__ mask,
                                                       float* __restrict__ out) {
    const int n1 = blockIdx.x;
    const int p  = threadIdx.x;
    const int lane = p & 31;
    const int warp = p >> 5;
    __shared__ float wmax[32][16];
    __shared__ float score[16];

    float mk = mask[n1 * PP + p];
    float sum = 0.f;
    float sps[16];
#pragma unroll
    for (int l = 0; l < LL; l++)
#pragma unroll
        for (int n2 = 0; n2 < NN2; n2++) {
            int w = l * NN2 + n2;
            int pr = (l * NN1 + n1) * NN2 + n2;
            float s = fmaxf(g_md2[pr * PP + p], g_md2[128 * PP + pr * PP + p]);
            float d2 = fmaxf(2.0f - 2.0f * s, 1e-12f);
            float sp = sqrtf(d2) * 0.5f * mk;
            sum += sp;
            sps[w] = sp;
        }
    g_spbar[n1 * PP + p] = sum * (1.0f / 16.0f);

#pragma unroll
    for (int o = 16; o > 0; o >>= 1)
#pragma unroll
        for (int w = 0; w < 16; w++)
            sps[w] = fmaxf(sps[w], __shfl_xor_sync(0xffffffffu, sps[w], o));
    if (lane == 0)
#pragma unroll
        for (int w = 0; w < 16; w++) wmax[warp][w] = sps[w];
    __syncthreads();

    if (warp < 16) {
        float m = wmax[lane][warp];
#pragma unroll
        for (int o = 16; o > 0; o >>= 1)
            m = fmaxf(m, __shfl_xor_sync(0xffffffffu, m, o));
        if (lane == 0) score[warp] = m;
    }
    __syncthreads();
    if (p == 0) {
        float s = 0.f;
#pragma unroll
        for (int w = 0; w < 16; w++) s += score[w];
        out[n1] = s * (1.0f / 16.0f);
    }
}

// ---------------------------------------------------------------------------
// Kernel 4: bilinear resize 32x32 -> 512x512, 4 px per thread (float4 store).
// ---------------------------------------------------------------------------
__global__ __launch_bounds__(256) void resize_kernel(float* __restrict__ out) {
    int idx = blockIdx.x * 256 + threadIdx.x;          // NN1*512*128 threads
    if (idx >= NN1 * IMG * (IMG / 4)) return;
    int n1  = idx >> 16;                // 512*128 per n1
    int rem = idx & 65535;
    int y  = rem >> 7;
    int xq = rem & 127;

    float sy = (y + 0.5f) * (1.0f / 16.0f) - 0.5f;
    int y0 = (int)floorf(sy);
    float wy = sy - (float)y0;
    int y0c = min(max(y0, 0), PH - 1);
    int y1c = min(max(y0 + 1, 0), PH - 1);

    const float* r0 = g_spbar + n1 * PP + y0c * PW;
    const float* r1 = g_spbar + n1 * PP + y1c * PW;

    float res[4];
#pragma unroll
    for (int j = 0; j < 4; j++) {
        int x = xq * 4 + j;
        float sx = (x + 0.5f) * (1.0f / 16.0f) - 0.5f;
        int x0 = (int)floorf(sx);
        float wx = sx - (float)x0;
        int x0c = min(max(x0, 0), PW - 1);
        int x1c = min(max(x0 + 1, 0), PW - 1);
        float top = (1.f - wx) * r0[x0c] + wx * r0[x1c];
        float bot = (1.f - wx) * r1[x0c] + wx * r1[x1c];
        res[j] = (1.f - wy) * top + wy * bot;
    }
    float4 v4 = make_float4(res[0], res[1], res[2], res[3]);
    *(float4*)(out + 8 + (size_t)n1 * IMG * IMG + y * IMG + xq * 4) = v4;
}

// ---------------------------------------------------------------------------
extern "C" void kernel_launch(void* const* d_in, const int* in_sizes, int n_in,
                              void* d_out, int out_size) {
    const float* feats  = (const float*)d_in[0];
    const float* nfeats = (const float*)d_in[1];
    const float* mask   = (const float*)d_in[2];
    float* out = (float*)d_out;

    const int rows = LL * NN1 * PP;  // 16384 rows per tensor

    dim3 ngrid(rows / 8, 2);
    normalize_kernel<<<ngrid, 256>>>(feats, nfeats, rows);

    cudaFuncSetAttribute(distmax_bf16_v10,
                         cudaFuncAttributeMaxDynamicSharedMemorySize, SMEM_BYTES);
    dim3 grid(16, LL * NN1 * NN2);  // (rowblk x colhalf, 128 pairs) = 2048 CTAs
    distmax_bf16_v10<<<grid, 256, SMEM_BYTES>>>();

    spfused_kernel<<<NN1, 1024>>>(mask, out);
    resize_kernel<<<(NN1 * IMG * (IMG / 4) + 255) / 256, 256>>>(out);
}